// round 14
// baseline (speedup 1.0000x reference)
#include <cuda_runtime.h>
#include <cuda_bf16.h>
#include <cstdint>

#define N_NODES 10000
#define N_EDGES 640000
#define DIM 128
#define NHEADS 8

typedef unsigned long long u64;

// ---------------- scratch (device globals; no allocation allowed) ----------------
__device__ float g_Q[N_NODES * DIM];
__device__ float g_K[N_NODES * DIM];
__device__ float g_V[N_NODES * DIM];
__device__ float g_s[(size_t)N_EDGES * NHEADS];
__device__ int   g_cnt[N_NODES];
__device__ int   g_start[N_NODES];
__device__ int   g_cursor[N_NODES];
__device__ int   g_elist[N_EDGES];
// We split into bf16 hi/lo, compact row-major [n=128][k=128]
__device__ __align__(16) __nv_bfloat16 g_Bhi[DIM * DIM];
__device__ __align__(16) __nv_bfloat16 g_Blo[DIM * DIM];

// ---------------- fp32x2 helpers (QKV FFMA GEMM) ----------------
__device__ __forceinline__ u64 pack_dup(float a) {
    u64 r; asm("mov.b64 %0, {%1, %1};" : "=l"(r) : "f"(a)); return r;
}
__device__ __forceinline__ u64 fma2(u64 a, u64 b, u64 c) {
    u64 d; asm("fma.rn.f32x2 %0, %1, %2, %3;" : "=l"(d) : "l"(a), "l"(b), "l"(c)); return d;
}
__device__ __forceinline__ float2 unpack2(u64 v) {
    float lo, hi; asm("mov.b64 {%0, %1}, %2;" : "=f"(lo), "=f"(hi) : "l"(v));
    return make_float2(lo, hi);
}

// ---------------- bf16 mma.sync + ldmatrix (sm_80+ PTX, legal on target sm_103) ------
__device__ __forceinline__ void mma_bf16(float* c, const uint32_t* a,
                                         uint32_t b0, uint32_t b1) {
    asm volatile(
        "mma.sync.aligned.m16n8k16.row.col.f32.bf16.bf16.f32 "
        "{%0,%1,%2,%3}, {%4,%5,%6,%7}, {%8,%9}, {%0,%1,%2,%3};"
        : "+f"(c[0]), "+f"(c[1]), "+f"(c[2]), "+f"(c[3])
        : "r"(a[0]), "r"(a[1]), "r"(a[2]), "r"(a[3]), "r"(b0), "r"(b1));
}

__device__ __forceinline__ void ldsm4(uint32_t& r0, uint32_t& r1, uint32_t& r2,
                                      uint32_t& r3, uint32_t addr) {
    asm volatile("ldmatrix.sync.aligned.m8n8.x4.shared.b16 {%0,%1,%2,%3}, [%4];"
                 : "=r"(r0), "=r"(r1), "=r"(r2), "=r"(r3) : "r"(addr));
}

__device__ __forceinline__ uint32_t smem_u32(const void* p) {
    uint32_t a;
    asm("{ .reg .u64 t; cvta.to.shared.u64 t, %1; cvt.u32.u64 %0, t; }" : "=r"(a) : "l"(p));
    return a;
}

// XOR swizzle for 256B bf16 rows (conflict-free frag loads)
__device__ __forceinline__ int swz(int row, int kb) {
    return row * 256 + (kb ^ ((row & 7) << 4));
}

// split a float2 into bf16 hi-pair / lo-pair (packed u32 each)
__device__ __forceinline__ void split2(float2 v, uint32_t& hi, uint32_t& lo) {
    __nv_bfloat162 h = __floats2bfloat162_rn(v.x, v.y);
    float r0 = v.x - __bfloat162float(h.x);
    float r1 = v.y - __bfloat162float(h.y);
    __nv_bfloat162 l = __floats2bfloat162_rn(r0, r1);
    hi = *(uint32_t*)&h;
    lo = *(uint32_t*)&l;
}

// ---------------- prep: split We into bf16 hi/lo + zero CSR counters ----------------
__global__ void prep_we_kernel(const float* __restrict__ We) {
    int idx = blockIdx.x * blockDim.x + threadIdx.x;
    if (idx < N_NODES) { g_cnt[idx] = 0; g_cursor[idx] = 0; }
    if (idx >= DIM * DIM) return;
    float f = We[idx];
    __nv_bfloat16 hi = __float2bfloat16(f);
    __nv_bfloat16 lo = __float2bfloat16(f - __bfloat162float(hi));
    g_Bhi[idx] = hi;
    g_Blo[idx] = lo;
}

// ---------------- QKV projections (FFMA, small) ----------------
#define SPAD 132
template <bool GUARD>
__device__ __forceinline__ void load_slab(const float* __restrict__ src, int row0,
                                          int maxrow, int j0,
                                          float (*dst)[SPAD], int tid) {
#pragma unroll
    for (int r = 0; r < 4; r++) {
        int idx = tid + r * 256;
        int row = idx >> 3;
        int jq  = idx & 7;
        float4 v = make_float4(0.f, 0.f, 0.f, 0.f);
        int gr = row0 + row;
        if (!GUARD || gr < maxrow)
            v = *(const float4*)(src + (size_t)gr * DIM + j0 + jq * 4);
        dst[jq * 4 + 0][row] = v.x;
        dst[jq * 4 + 1][row] = v.y;
        dst[jq * 4 + 2][row] = v.z;
        dst[jq * 4 + 3][row] = v.w;
    }
}

__device__ __forceinline__ void gemm_inner(const float (*As)[SPAD],
                                           const float (*Ws)[SPAD],
                                           u64 acc[8][4], int tx, int ty) {
#pragma unroll 4
    for (int j = 0; j < 32; j++) {
        float4 a0 = *(const float4*)&As[j][ty * 8];
        float4 a1 = *(const float4*)&As[j][ty * 8 + 4];
        const u64* wp = (const u64*)&Ws[j][tx * 8];
        u64 w0 = wp[0], w1 = wp[1], w2 = wp[2], w3 = wp[3];
        float a[8] = {a0.x, a0.y, a0.z, a0.w, a1.x, a1.y, a1.z, a1.w};
#pragma unroll
        for (int i = 0; i < 8; i++) {
            u64 ad = pack_dup(a[i]);
            acc[i][0] = fma2(ad, w0, acc[i][0]);
            acc[i][1] = fma2(ad, w1, acc[i][1]);
            acc[i][2] = fma2(ad, w2, acc[i][2]);
            acc[i][3] = fma2(ad, w3, acc[i][3]);
        }
    }
}

__global__ __launch_bounds__(256, 2) void qkv_kernel(
    const float* __restrict__ h,
    const float* __restrict__ Wq, const float* __restrict__ bq,
    const float* __restrict__ Wk, const float* __restrict__ bk,
    const float* __restrict__ Wv, const float* __restrict__ bv) {
    __shared__ float As[32][SPAD];
    __shared__ float Ws[32][SPAD];

    const float* W; const float* b; float* out;
    if (blockIdx.y == 0)      { W = Wq; b = bq; out = g_Q; }
    else if (blockIdx.y == 1) { W = Wk; b = bk; out = g_K; }
    else                      { W = Wv; b = bv; out = g_V; }

    int tid = threadIdx.x;
    int tx = tid & 15, ty = tid >> 4;
    int m0 = blockIdx.x * 128;

    u64 acc[8][4];
#pragma unroll
    for (int i = 0; i < 8; i++)
#pragma unroll
        for (int k = 0; k < 4; k++) acc[i][k] = 0ull;

    for (int kt = 0; kt < 4; kt++) {
        load_slab<true>(h, m0, N_NODES, kt * 32, As, tid);
        load_slab<false>(W, 0, 128, kt * 32, Ws, tid);
        __syncthreads();
        gemm_inner(As, Ws, acc, tx, ty);
        __syncthreads();
    }

    float4 b0 = *(const float4*)(b + tx * 8);
    float4 b1 = *(const float4*)(b + tx * 8 + 4);
#pragma unroll
    for (int i = 0; i < 8; i++) {
        int m = m0 + ty * 8 + i;
        if (m < N_NODES) {
            float2 p0 = unpack2(acc[i][0]);
            float2 p1 = unpack2(acc[i][1]);
            float2 p2 = unpack2(acc[i][2]);
            float2 p3 = unpack2(acc[i][3]);
            float4 o0 = make_float4(p0.x + b0.x, p0.y + b0.y, p1.x + b0.z, p1.y + b0.w);
            float4 o1 = make_float4(p2.x + b1.x, p2.y + b1.y, p3.x + b1.z, p3.y + b1.w);
            *(float4*)(out + (size_t)m * DIM + tx * 8)     = o0;
            *(float4*)(out + (size_t)m * DIM + tx * 8 + 4) = o1;
        }
    }
}

// ---------------- edge projection: mma.sync bf16x3, M=64 x N=64 per warp ------------
// 4 warps = 2 rowgroups (64 edges) x 2 colhalves (64 cols / 4 heads).
// Dynamic smem: B_hi [0,32KB), B_lo [32KB,64KB). 128 threads, 2 CTAs/SM.
#define SM_BLO_OFF 32768
#define SMEM_EDGE_TOTAL 65536

__global__ __launch_bounds__(128, 2)
void edge_score_mma_kernel(const float* __restrict__ e,
                           const float* __restrict__ be,
                           const int* __restrict__ src,
                           const int* __restrict__ dst) {
    extern __shared__ char smem[];
    int tid = threadIdx.x;
    int lane = tid & 31;
    int wid = tid >> 5;
    int rg = wid >> 1;       // row group: edges [rg*64, rg*64+64)
    int ch = wid & 1;        // col half: cols [ch*64, ch*64+64) = heads [ch*4, ch*4+4)

    // --- copy We hi/lo into swizzled smem (64KB, L2-resident source) ---
    {
        const uint4* sh = (const uint4*)g_Bhi;
        const uint4* sl = (const uint4*)g_Blo;
#pragma unroll
        for (int it = 0; it < 16; it++) {
            int i = tid + it * 128;      // 2048 16B-chunks each array
            int row = i >> 4, q = i & 15;
            int off = swz(row, q * 16);
            *(uint4*)(smem + off) = sh[i];
            *(uint4*)(smem + SM_BLO_OFF + off) = sl[i];
        }
    }
    __syncthreads();

    // --- fragment geometry ---
    int qd = lane & 3;                     // quad lane
    int wm = rg * 64 + (lane >> 2);        // row streams: wm + mt*16 + {0,8}, mt=0..3
    int e0 = blockIdx.x * 128 + wm;
    const float* eBase = e + (size_t)e0 * DIM + qd * 2;

    // per-lane ldmatrix base: lanes 0-7 Bh k-chunk0, 8-15 Bh k-chunk1,
    //                         16-23 Bl chunk0, 24-31 Bl chunk1; + colhalf offset
    int lr = lane & 7;
    int sel = lane >> 3;
    uint32_t sb = smem_u32(smem);
    uint32_t ldbase = sb + ((sel >> 1) ? SM_BLO_OFF : 0) + lr * 256 + ch * 16384;
    int sel1 = (sel & 1) * 16;

    float acc[4][8][4];   // [m-tile][n-frag][frag regs]
#pragma unroll
    for (int mt = 0; mt < 4; mt++)
#pragma unroll
        for (int j = 0; j < 8; j++)
#pragma unroll
            for (int k = 0; k < 4; k++) acc[mt][j][k] = 0.f;

    // prefetch A for (mt=0, ks=0)
    float2 fcur[4], fnxt[4];
    fcur[0] = *(const float2*)(eBase);
    fcur[1] = *(const float2*)(eBase + 8 * DIM);
    fcur[2] = *(const float2*)(eBase + 8);
    fcur[3] = *(const float2*)(eBase + 8 * DIM + 8);

#pragma unroll 1
    for (int ks = 0; ks < 8; ks++) {
        // load all 8 B fragment sets for this ks once; reuse across 4 m-tiles
        uint32_t lda = ldbase + ((uint32_t)(ks * 32 + sel1) ^ (uint32_t)(lr * 16));
        uint32_t bh0[8], bh1[8], bl0[8], bl1[8];
#pragma unroll
        for (int j = 0; j < 8; j++)
            ldsm4(bh0[j], bh1[j], bl0[j], bl1[j], lda + j * 2048);

#pragma unroll
        for (int mt = 0; mt < 4; mt++) {
            // software pipeline: prefetch next m-tile's A (or next ks, mt0)
            int nmt = (mt + 1) & 3;
            int nks = (mt == 3) ? ks + 1 : ks;
            if (nks < 8) {
                const float* p = eBase + nmt * 16 * DIM + nks * 16;
                fnxt[0] = *(const float2*)(p);
                fnxt[1] = *(const float2*)(p + 8 * DIM);
                fnxt[2] = *(const float2*)(p + 8);
                fnxt[3] = *(const float2*)(p + 8 * DIM + 8);
            }
            uint32_t ah[4], al[4];
            split2(fcur[0], ah[0], al[0]);
            split2(fcur[1], ah[1], al[1]);
            split2(fcur[2], ah[2], al[2]);
            split2(fcur[3], ah[3], al[3]);
#pragma unroll
            for (int j = 0; j < 8; j++) {
                mma_bf16(acc[mt][j], ah, bh0[j], bh1[j]);
                mma_bf16(acc[mt][j], ah, bl0[j], bl1[j]);
                mma_bf16(acc[mt][j], al, bh0[j], bh1[j]);
            }
#pragma unroll
            for (int q = 0; q < 4; q++) fcur[q] = fnxt[q];
        }
    }

    // --- register epilogue: warp owns heads [ch*4, ch*4+4) completely ---
    float2 bb[8];
#pragma unroll
    for (int j = 0; j < 8; j++)
        bb[j] = *(const float2*)(be + (ch * 8 + j) * 8 + qd * 2);

#pragma unroll
    for (int mt = 0; mt < 4; mt++) {
        int rA = e0 + mt * 16;
        int rB = rA + 8;
        int sA = src[rA], dA = dst[rA];
        int sB = src[rB], dB = dst[rB];
        const float* KA = g_K + (size_t)sA * DIM + ch * 64 + qd * 2;
        const float* QA = g_Q + (size_t)dA * DIM + ch * 64 + qd * 2;
        const float* KB = g_K + (size_t)sB * DIM + ch * 64 + qd * 2;
        const float* QB = g_Q + (size_t)dB * DIM + ch * 64 + qd * 2;

        float hsA[4] = {0.f, 0.f, 0.f, 0.f};
        float hsB[4] = {0.f, 0.f, 0.f, 0.f};
#pragma unroll
        for (int j = 0; j < 8; j++) {
            int c = j * 8;
            float2 K0 = *(const float2*)(KA + c);
            float2 Q0 = *(const float2*)(QA + c);
            float2 K1 = *(const float2*)(KB + c);
            float2 Q1 = *(const float2*)(QB + c);
            int hh = j >> 1;
            hsA[hh] += (acc[mt][j][0] + bb[j].x) * K0.x * Q0.x +
                       (acc[mt][j][1] + bb[j].y) * K0.y * Q0.y;
            hsB[hh] += (acc[mt][j][2] + bb[j].x) * K1.x * Q1.x +
                       (acc[mt][j][3] + bb[j].y) * K1.y * Q1.y;
        }
        // quad reduction over d within each head
#pragma unroll
        for (int hh = 0; hh < 4; hh++) {
            hsA[hh] += __shfl_xor_sync(0xffffffffu, hsA[hh], 1);
            hsA[hh] += __shfl_xor_sync(0xffffffffu, hsA[hh], 2);
            hsB[hh] += __shfl_xor_sync(0xffffffffu, hsB[hh], 1);
            hsB[hh] += __shfl_xor_sync(0xffffffffu, hsB[hh], 2);
        }
        // quad lane qd writes head ch*4+qd for both rows
        float vA = 0.f, vB = 0.f;
#pragma unroll
        for (int x = 0; x < 4; x++) {
            if (x == qd) { vA = hsA[x]; vB = hsB[x]; }
        }
        int hh = ch * 4 + qd;
        float scA = fminf(fmaxf(vA * 0.25f, -5.0f), 5.0f);
        float scB = fminf(fmaxf(vB * 0.25f, -5.0f), 5.0f);
        g_s[(size_t)rA * NHEADS + hh] = __expf(scA);
        g_s[(size_t)rB * NHEADS + hh] = __expf(scB);
    }
}

// ---------------- CSR build (by dst) ----------------
__global__ void hist_kernel(const int* __restrict__ dst) {
    int e0 = blockIdx.x * blockDim.x + threadIdx.x;
    if (e0 < N_EDGES) atomicAdd(&g_cnt[dst[e0]], 1);
}

__global__ void scan_kernel() {
    __shared__ int sm[1024];
    int t = threadIdx.x;
    const int CH = 10;
    int base = t * CH;
    int s = 0;
#pragma unroll
    for (int c = 0; c < CH; c++) {
        int i = base + c;
        if (i < N_NODES) s += g_cnt[i];
    }
    sm[t] = s;
    __syncthreads();
    for (int off = 1; off < 1024; off <<= 1) {
        int v = (t >= off) ? sm[t - off] : 0;
        __syncthreads();
        sm[t] += v;
        __syncthreads();
    }
    int run = sm[t] - s;
#pragma unroll
    for (int c = 0; c < CH; c++) {
        int i = base + c;
        if (i < N_NODES) {
            g_start[i] = run;
            run += g_cnt[i];
        }
    }
}

__global__ void scatter_kernel(const int* __restrict__ dst) {
    int e0 = blockIdx.x * blockDim.x + threadIdx.x;
    if (e0 < N_EDGES) {
        int d = dst[e0];
        int p = atomicAdd(&g_cursor[d], 1);
        g_elist[g_start[d] + p] = e0;
    }
}

// ---------------- per-dst gather aggregation (unroll-4 MLP) ----------------
__global__ void aggregate_kernel(const int* __restrict__ src,
                                 float* __restrict__ out) {
    int warp = (blockIdx.x * blockDim.x + threadIdx.x) >> 5;
    int lane = threadIdx.x & 31;
    if (warp >= N_NODES) return;
    int st = g_start[warp];
    int cn = g_cnt[warp];
    int hh = lane >> 2;
    float a0 = 0.f, a1 = 0.f, a2 = 0.f, a3 = 0.f, z = 0.f;
    int k = 0;
    for (; k + 4 <= cn; k += 4) {
        int i0 = g_elist[st + k];
        int i1 = g_elist[st + k + 1];
        int i2 = g_elist[st + k + 2];
        int i3 = g_elist[st + k + 3];
        float s0 = g_s[(size_t)i0 * NHEADS + hh];
        float s1 = g_s[(size_t)i1 * NHEADS + hh];
        float s2 = g_s[(size_t)i2 * NHEADS + hh];
        float s3 = g_s[(size_t)i3 * NHEADS + hh];
        float4 v0 = *(const float4*)(g_V + (size_t)src[i0] * DIM + lane * 4);
        float4 v1 = *(const float4*)(g_V + (size_t)src[i1] * DIM + lane * 4);
        float4 v2 = *(const float4*)(g_V + (size_t)src[i2] * DIM + lane * 4);
        float4 v3 = *(const float4*)(g_V + (size_t)src[i3] * DIM + lane * 4);
        a0 += v0.x * s0 + v1.x * s1 + v2.x * s2 + v3.x * s3;
        a1 += v0.y * s0 + v1.y * s1 + v2.y * s2 + v3.y * s3;
        a2 += v0.z * s0 + v1.z * s1 + v2.z * s2 + v3.z * s3;
        a3 += v0.w * s0 + v1.w * s1 + v2.w * s2 + v3.w * s3;
        z += s0 + s1 + s2 + s3;
    }
    for (; k < cn; k++) {
        int eidx = g_elist[st + k];
        float s = g_s[(size_t)eidx * NHEADS + hh];
        float4 v = *(const float4*)(g_V + (size_t)src[eidx] * DIM + lane * 4);
        a0 += v.x * s;
        a1 += v.y * s;
        a2 += v.z * s;
        a3 += v.w * s;
        z += s;
    }
    float inv = 1.0f / (z + 1e-6f);
    float4 o = make_float4(a0 * inv, a1 * inv, a2 * inv, a3 * inv);
    *(float4*)(out + (size_t)warp * DIM + lane * 4) = o;
}

// ---------------- launch ----------------
extern "C" void kernel_launch(void* const* d_in, const int* in_sizes, int n_in,
                              void* d_out, int out_size) {
    const float* h  = (const float*)d_in[0];
    const float* e  = (const float*)d_in[1];
    const int*   src = (const int*)d_in[2];
    const int*   dst = (const int*)d_in[3];
    const float* Wq = (const float*)d_in[4];
    const float* bq = (const float*)d_in[5];
    const float* Wk = (const float*)d_in[6];
    const float* bk = (const float*)d_in[7];
    const float* We = (const float*)d_in[8];
    const float* be = (const float*)d_in[9];
    const float* Wv = (const float*)d_in[10];
    const float* bv = (const float*)d_in[11];
    float* out = (float*)d_out;

    cudaFuncSetAttribute(edge_score_mma_kernel,
                         cudaFuncAttributeMaxDynamicSharedMemorySize, SMEM_EDGE_TOTAL);

    // edge kernel at launch index 3 — the slot ncu's -s 5 -c 1 capture lands on
    prep_we_kernel<<<(DIM * DIM + 255) / 256, 256>>>(We);               // 0 (+ zeroes cnt)
    dim3 gq((N_NODES + 127) / 128, 3);
    qkv_kernel<<<gq, 256>>>(h, Wq, bq, Wk, bk, Wv, bv);                 // 1
    hist_kernel<<<(N_EDGES + 255) / 256, 256>>>(dst);                   // 2
    edge_score_mma_kernel<<<N_EDGES / 128, 128, SMEM_EDGE_TOTAL>>>(e, be, src, dst);  // 3
    scan_kernel<<<1, 1024>>>();                                         // 4
    scatter_kernel<<<(N_EDGES + 255) / 256, 256>>>(dst);                // 5
    aggregate_kernel<<<(N_NODES * 32 + 255) / 256, 256>>>(src, out);    // 6
}

// round 15
// speedup vs baseline: 1.6194x; 1.6194x over previous
#include <cuda_runtime.h>
#include <cuda_bf16.h>
#include <cstdint>

#define N_NODES 10000
#define N_EDGES 640000
#define DIM 128
#define NHEADS 8

typedef unsigned long long u64;

// ---------------- scratch (device globals; no allocation allowed) ----------------
__device__ float g_Q[N_NODES * DIM];
__device__ float g_K[N_NODES * DIM];
__device__ float g_V[N_NODES * DIM];
__device__ float g_s[(size_t)N_EDGES * NHEADS];
__device__ int   g_cnt[N_NODES];
__device__ int   g_start[N_NODES];
__device__ int   g_cursor[N_NODES];
__device__ int   g_elist[N_EDGES];
// We split into bf16 hi/lo, rows COLUMN-PERMUTED: storage slot s holds original
// output column sigma(s) = 32*((s&7)>>1) + 2*(s>>3) + (s&1).  With the m16n8k16
// fragment map (lane quad qd owns cols 8n+2qd+{0,1}), this gives lane qd the
// original contiguous columns [32qd, 32qd+32) == heads 2qd, 2qd+1.
__device__ __align__(16) __nv_bfloat16 g_Bhi[DIM * DIM];
__device__ __align__(16) __nv_bfloat16 g_Blo[DIM * DIM];

// ---------------- fp32x2 helpers (QKV FFMA GEMM) ----------------
__device__ __forceinline__ u64 pack_dup(float a) {
    u64 r; asm("mov.b64 %0, {%1, %1};" : "=l"(r) : "f"(a)); return r;
}
__device__ __forceinline__ u64 fma2(u64 a, u64 b, u64 c) {
    u64 d; asm("fma.rn.f32x2 %0, %1, %2, %3;" : "=l"(d) : "l"(a), "l"(b), "l"(c)); return d;
}
__device__ __forceinline__ float2 unpack2(u64 v) {
    float lo, hi; asm("mov.b64 {%0, %1}, %2;" : "=f"(lo), "=f"(hi) : "l"(v));
    return make_float2(lo, hi);
}

// ---------------- bf16 mma.sync + ldmatrix (sm_80+ PTX, legal on target sm_103) ------
__device__ __forceinline__ void mma_bf16(float* c, const uint32_t* a,
                                         uint32_t b0, uint32_t b1) {
    asm volatile(
        "mma.sync.aligned.m16n8k16.row.col.f32.bf16.bf16.f32 "
        "{%0,%1,%2,%3}, {%4,%5,%6,%7}, {%8,%9}, {%0,%1,%2,%3};"
        : "+f"(c[0]), "+f"(c[1]), "+f"(c[2]), "+f"(c[3])
        : "r"(a[0]), "r"(a[1]), "r"(a[2]), "r"(a[3]), "r"(b0), "r"(b1));
}

__device__ __forceinline__ void ldsm4(uint32_t& r0, uint32_t& r1, uint32_t& r2,
                                      uint32_t& r3, uint32_t addr) {
    asm volatile("ldmatrix.sync.aligned.m8n8.x4.shared.b16 {%0,%1,%2,%3}, [%4];"
                 : "=r"(r0), "=r"(r1), "=r"(r2), "=r"(r3) : "r"(addr));
}

__device__ __forceinline__ uint32_t smem_u32(const void* p) {
    uint32_t a;
    asm("{ .reg .u64 t; cvta.to.shared.u64 t, %1; cvt.u32.u64 %0, t; }" : "=r"(a) : "l"(p));
    return a;
}

// XOR swizzle for 256B bf16 rows (conflict-free frag loads)
__device__ __forceinline__ int swz(int row, int kb) {
    return row * 256 + (kb ^ ((row & 7) << 4));
}

// split a float2 into bf16 hi-pair / lo-pair (packed u32 each)
__device__ __forceinline__ void split2(float2 v, uint32_t& hi, uint32_t& lo) {
    __nv_bfloat162 h = __floats2bfloat162_rn(v.x, v.y);
    float r0 = v.x - __bfloat162float(h.x);
    float r1 = v.y - __bfloat162float(h.y);
    __nv_bfloat162 l = __floats2bfloat162_rn(r0, r1);
    hi = *(uint32_t*)&h;
    lo = *(uint32_t*)&l;
}

// ---------------- prep: split We into bf16 hi/lo (col-permuted) + zero counters ------
__global__ void prep_we_kernel(const float* __restrict__ We) {
    int idx = blockIdx.x * blockDim.x + threadIdx.x;
    if (idx < N_NODES) { g_cnt[idx] = 0; g_cursor[idx] = 0; }
    if (idx >= DIM * DIM) return;
    int s = idx >> 7, k = idx & 127;
    int o = ((s >> 1) & 3) * 32 + (s >> 3) * 2 + (s & 1);   // sigma(s)
    float f = We[o * DIM + k];
    __nv_bfloat16 hi = __float2bfloat16(f);
    __nv_bfloat16 lo = __float2bfloat16(f - __bfloat162float(hi));
    g_Bhi[idx] = hi;
    g_Blo[idx] = lo;
}

// ---------------- QKV projections (FFMA, small) ----------------
#define SPAD 132
template <bool GUARD>
__device__ __forceinline__ void load_slab(const float* __restrict__ src, int row0,
                                          int maxrow, int j0,
                                          float (*dst)[SPAD], int tid) {
#pragma unroll
    for (int r = 0; r < 4; r++) {
        int idx = tid + r * 256;
        int row = idx >> 3;
        int jq  = idx & 7;
        float4 v = make_float4(0.f, 0.f, 0.f, 0.f);
        int gr = row0 + row;
        if (!GUARD || gr < maxrow)
            v = *(const float4*)(src + (size_t)gr * DIM + j0 + jq * 4);
        dst[jq * 4 + 0][row] = v.x;
        dst[jq * 4 + 1][row] = v.y;
        dst[jq * 4 + 2][row] = v.z;
        dst[jq * 4 + 3][row] = v.w;
    }
}

__device__ __forceinline__ void gemm_inner(const float (*As)[SPAD],
                                           const float (*Ws)[SPAD],
                                           u64 acc[8][4], int tx, int ty) {
#pragma unroll 4
    for (int j = 0; j < 32; j++) {
        float4 a0 = *(const float4*)&As[j][ty * 8];
        float4 a1 = *(const float4*)&As[j][ty * 8 + 4];
        const u64* wp = (const u64*)&Ws[j][tx * 8];
        u64 w0 = wp[0], w1 = wp[1], w2 = wp[2], w3 = wp[3];
        float a[8] = {a0.x, a0.y, a0.z, a0.w, a1.x, a1.y, a1.z, a1.w};
#pragma unroll
        for (int i = 0; i < 8; i++) {
            u64 ad = pack_dup(a[i]);
            acc[i][0] = fma2(ad, w0, acc[i][0]);
            acc[i][1] = fma2(ad, w1, acc[i][1]);
            acc[i][2] = fma2(ad, w2, acc[i][2]);
            acc[i][3] = fma2(ad, w3, acc[i][3]);
        }
    }
}

__global__ __launch_bounds__(256, 2) void qkv_kernel(
    const float* __restrict__ h,
    const float* __restrict__ Wq, const float* __restrict__ bq,
    const float* __restrict__ Wk, const float* __restrict__ bk,
    const float* __restrict__ Wv, const float* __restrict__ bv) {
    __shared__ float As[32][SPAD];
    __shared__ float Ws[32][SPAD];

    const float* W; const float* b; float* out;
    if (blockIdx.y == 0)      { W = Wq; b = bq; out = g_Q; }
    else if (blockIdx.y == 1) { W = Wk; b = bk; out = g_K; }
    else                      { W = Wv; b = bv; out = g_V; }

    int tid = threadIdx.x;
    int tx = tid & 15, ty = tid >> 4;
    int m0 = blockIdx.x * 128;

    u64 acc[8][4];
#pragma unroll
    for (int i = 0; i < 8; i++)
#pragma unroll
        for (int k = 0; k < 4; k++) acc[i][k] = 0ull;

    for (int kt = 0; kt < 4; kt++) {
        load_slab<true>(h, m0, N_NODES, kt * 32, As, tid);
        load_slab<false>(W, 0, 128, kt * 32, Ws, tid);
        __syncthreads();
        gemm_inner(As, Ws, acc, tx, ty);
        __syncthreads();
    }

    float4 b0 = *(const float4*)(b + tx * 8);
    float4 b1 = *(const float4*)(b + tx * 8 + 4);
#pragma unroll
    for (int i = 0; i < 8; i++) {
        int m = m0 + ty * 8 + i;
        if (m < N_NODES) {
            float2 p0 = unpack2(acc[i][0]);
            float2 p1 = unpack2(acc[i][1]);
            float2 p2 = unpack2(acc[i][2]);
            float2 p3 = unpack2(acc[i][3]);
            float4 o0 = make_float4(p0.x + b0.x, p0.y + b0.y, p1.x + b0.z, p1.y + b0.w);
            float4 o1 = make_float4(p2.x + b1.x, p2.y + b1.y, p3.x + b1.z, p3.y + b1.w);
            *(float4*)(out + (size_t)m * DIM + tx * 8)     = o0;
            *(float4*)(out + (size_t)m * DIM + tx * 8 + 4) = o1;
        }
    }
}

// ---------------- edge projection: mma.sync bf16x3, M=32/warp, 3 CTAs/SM ------------
// Col-permuted B -> lane quad qd owns original cols [32qd,32qd+32) = heads 2qd,2qd+1.
// Dynamic smem: B_hi [0,32KB), B_lo [32KB,64KB) — 128 threads, 3 CTAs/SM (12 warps).
#define SM_BLO_OFF 32768
#define SMEM_EDGE_TOTAL 65536

__global__ __launch_bounds__(128, 3)
void edge_score_mma_kernel(const float* __restrict__ e,
                           const float* __restrict__ be,
                           const int* __restrict__ src,
                           const int* __restrict__ dst) {
    extern __shared__ char smem[];
    int tid = threadIdx.x;
    int lane = tid & 31;
    int wid = tid >> 5;

    // --- copy We hi/lo into swizzled smem (64KB, L2-resident source) ---
    {
        const uint4* sh = (const uint4*)g_Bhi;
        const uint4* sl = (const uint4*)g_Blo;
#pragma unroll
        for (int it = 0; it < 16; it++) {
            int i = tid + it * 128;      // 2048 16B-chunks each array
            int row = i >> 4, q = i & 15;
            int off = swz(row, q * 16);
            *(uint4*)(smem + off) = sh[i];
            *(uint4*)(smem + SM_BLO_OFF + off) = sl[i];
        }
    }
    __syncthreads();

    // --- fragment geometry: warp owns rows [wid*32, wid*32+32) (2 m16 tiles) ---
    int qd = lane & 3;                    // quad lane
    int wm = wid * 32 + (lane >> 2);      // tile0 rows: wm, wm+8; tile1: wm+16, wm+24
    int e0 = blockIdx.x * 128 + wm;
    const float* eBase = e + (size_t)e0 * DIM + qd * 2;  // rows via immediate offsets

    // per-lane ldmatrix base: lanes 0-7 Bh k-chunk0, 8-15 Bh k-chunk1,
    //                         16-23 Bl chunk0, 24-31 Bl chunk1
    int lr = lane & 7;
    int sel = lane >> 3;
    uint32_t sb = smem_u32(smem);
    uint32_t ldbase = sb + ((sel >> 1) ? SM_BLO_OFF : 0) + lr * 256;
    int sel1 = (sel & 1) * 16;

    float acc0[16][4], acc1[16][4];
#pragma unroll
    for (int n = 0; n < 16; n++)
#pragma unroll
        for (int j = 0; j < 4; j++) { acc0[n][j] = 0.f; acc1[n][j] = 0.f; }

#pragma unroll 1
    for (int ks = 0; ks < 8; ks++) {
        int o = ks * 16;
        // A fragments straight from global (quad reads 32B-contiguous), split hi/lo
        float2 f0 = *(const float2*)(eBase + o);
        float2 f1 = *(const float2*)(eBase + o + 8 * DIM);
        float2 f2 = *(const float2*)(eBase + o + 8);
        float2 f3 = *(const float2*)(eBase + o + 8 * DIM + 8);
        float2 f4 = *(const float2*)(eBase + o + 16 * DIM);
        float2 f5 = *(const float2*)(eBase + o + 24 * DIM);
        float2 f6 = *(const float2*)(eBase + o + 16 * DIM + 8);
        float2 f7 = *(const float2*)(eBase + o + 24 * DIM + 8);
        uint32_t ah0[4], al0[4], ah1[4], al1[4];
        split2(f0, ah0[0], al0[0]);
        split2(f1, ah0[1], al0[1]);
        split2(f2, ah0[2], al0[2]);
        split2(f3, ah0[3], al0[3]);
        split2(f4, ah1[0], al1[0]);
        split2(f5, ah1[1], al1[1]);
        split2(f6, ah1[2], al1[2]);
        split2(f7, ah1[3], al1[3]);

        uint32_t lda = ldbase + ((uint32_t)(ks * 32 + sel1) ^ (uint32_t)(lr * 16));
#pragma unroll
        for (int n = 0; n < 16; n++) {
            uint32_t bh0, bh1, bl0, bl1;
            ldsm4(bh0, bh1, bl0, bl1, lda + n * 2048);
            mma_bf16(acc0[n], ah0, bh0, bh1);
            mma_bf16(acc0[n], ah0, bl0, bl1);
            mma_bf16(acc0[n], al0, bh0, bh1);
            mma_bf16(acc1[n], ah1, bh0, bh1);
            mma_bf16(acc1[n], ah1, bl0, bl1);
            mma_bf16(acc1[n], al1, bh0, bh1);
        }
    }

    // --- fold be into accumulators (orig cols 32qd+4jj..+3 map to slots n=2jj,2jj+1) --
    {
        const float4* be4 = (const float4*)(be + qd * 32);
#pragma unroll
        for (int jj = 0; jj < 8; jj++) {
            float4 b4 = be4[jj];
            acc0[2 * jj][0] += b4.x;     acc0[2 * jj][1] += b4.y;
            acc0[2 * jj + 1][0] += b4.z; acc0[2 * jj + 1][1] += b4.w;
            acc0[2 * jj][2] += b4.x;     acc0[2 * jj][3] += b4.y;
            acc0[2 * jj + 1][2] += b4.z; acc0[2 * jj + 1][3] += b4.w;
            acc1[2 * jj][0] += b4.x;     acc1[2 * jj][1] += b4.y;
            acc1[2 * jj + 1][0] += b4.z; acc1[2 * jj + 1][1] += b4.w;
            acc1[2 * jj][2] += b4.x;     acc1[2 * jj][3] += b4.y;
            acc1[2 * jj + 1][2] += b4.z; acc1[2 * jj + 1][3] += b4.w;
        }
    }

    // --- register epilogue, fully coalesced, no shfl: lane qd owns heads 2qd,2qd+1 ---
#pragma unroll
    for (int rr = 0; rr < 4; rr++) {
        int row = e0 + rr * 8;           // rows e0, e0+8 (acc0) / e0+16, e0+24 (acc1)
        int sn = src[row], dn = dst[row];
        const float4* Kp = (const float4*)(g_K + (size_t)sn * DIM + qd * 32);
        const float4* Qp = (const float4*)(g_Q + (size_t)dn * DIM + qd * 32);
        float hs0 = 0.f, hs1 = 0.f;
#pragma unroll
        for (int jj = 0; jj < 8; jj++) {
            float4 K4 = Kp[jj], Q4 = Qp[jj];
            const float* a0 = (rr < 2) ? acc0[2 * jj] : acc1[2 * jj];
            const float* a1 = (rr < 2) ? acc0[2 * jj + 1] : acc1[2 * jj + 1];
            int r0 = (rr & 1) * 2;
            float p = a0[r0] * K4.x * Q4.x + a0[r0 + 1] * K4.y * Q4.y +
                      a1[r0] * K4.z * Q4.z + a1[r0 + 1] * K4.w * Q4.w;
            if (jj < 4) hs0 += p; else hs1 += p;
        }
        float sc0 = fminf(fmaxf(hs0 * 0.25f, -5.0f), 5.0f);
        float sc1 = fminf(fmaxf(hs1 * 0.25f, -5.0f), 5.0f);
        g_s[(size_t)row * NHEADS + qd * 2 + 0] = __expf(sc0);
        g_s[(size_t)row * NHEADS + qd * 2 + 1] = __expf(sc1);
    }
}

// ---------------- CSR build (by dst) ----------------
__global__ void hist_kernel(const int* __restrict__ dst) {
    int e0 = blockIdx.x * blockDim.x + threadIdx.x;
    if (e0 < N_EDGES) atomicAdd(&g_cnt[dst[e0]], 1);
}

__global__ void scan_kernel() {
    __shared__ int sm[1024];
    int t = threadIdx.x;
    const int CH = 10;
    int base = t * CH;
    int s = 0;
#pragma unroll
    for (int c = 0; c < CH; c++) {
        int i = base + c;
        if (i < N_NODES) s += g_cnt[i];
    }
    sm[t] = s;
    __syncthreads();
    for (int off = 1; off < 1024; off <<= 1) {
        int v = (t >= off) ? sm[t - off] : 0;
        __syncthreads();
        sm[t] += v;
        __syncthreads();
    }
    int run = sm[t] - s;
#pragma unroll
    for (int c = 0; c < CH; c++) {
        int i = base + c;
        if (i < N_NODES) {
            g_start[i] = run;
            run += g_cnt[i];
        }
    }
}

__global__ void scatter_kernel(const int* __restrict__ dst) {
    int e0 = blockIdx.x * blockDim.x + threadIdx.x;
    if (e0 < N_EDGES) {
        int d = dst[e0];
        int p = atomicAdd(&g_cursor[d], 1);
        g_elist[g_start[d] + p] = e0;
    }
}

// ---------------- per-dst gather aggregation (unroll-4 MLP) ----------------
__global__ void aggregate_kernel(const int* __restrict__ src,
                                 float* __restrict__ out) {
    int warp = (blockIdx.x * blockDim.x + threadIdx.x) >> 5;
    int lane = threadIdx.x & 31;
    if (warp >= N_NODES) return;
    int st = g_start[warp];
    int cn = g_cnt[warp];
    int hh = lane >> 2;
    float a0 = 0.f, a1 = 0.f, a2 = 0.f, a3 = 0.f, z = 0.f;
    int k = 0;
    for (; k + 4 <= cn; k += 4) {
        int i0 = g_elist[st + k];
        int i1 = g_elist[st + k + 1];
        int i2 = g_elist[st + k + 2];
        int i3 = g_elist[st + k + 3];
        float s0 = g_s[(size_t)i0 * NHEADS + hh];
        float s1 = g_s[(size_t)i1 * NHEADS + hh];
        float s2 = g_s[(size_t)i2 * NHEADS + hh];
        float s3 = g_s[(size_t)i3 * NHEADS + hh];
        float4 v0 = *(const float4*)(g_V + (size_t)src[i0] * DIM + lane * 4);
        float4 v1 = *(const float4*)(g_V + (size_t)src[i1] * DIM + lane * 4);
        float4 v2 = *(const float4*)(g_V + (size_t)src[i2] * DIM + lane * 4);
        float4 v3 = *(const float4*)(g_V + (size_t)src[i3] * DIM + lane * 4);
        a0 += v0.x * s0 + v1.x * s1 + v2.x * s2 + v3.x * s3;
        a1 += v0.y * s0 + v1.y * s1 + v2.y * s2 + v3.y * s3;
        a2 += v0.z * s0 + v1.z * s1 + v2.z * s2 + v3.z * s3;
        a3 += v0.w * s0 + v1.w * s1 + v2.w * s2 + v3.w * s3;
        z += s0 + s1 + s2 + s3;
    }
    for (; k < cn; k++) {
        int eidx = g_elist[st + k];
        float s = g_s[(size_t)eidx * NHEADS + hh];
        float4 v = *(const float4*)(g_V + (size_t)src[eidx] * DIM + lane * 4);
        a0 += v.x * s;
        a1 += v.y * s;
        a2 += v.z * s;
        a3 += v.w * s;
        z += s;
    }
    float inv = 1.0f / (z + 1e-6f);
    float4 o = make_float4(a0 * inv, a1 * inv, a2 * inv, a3 * inv);
    *(float4*)(out + (size_t)warp * DIM + lane * 4) = o;
}

// ---------------- launch ----------------
extern "C" void kernel_launch(void* const* d_in, const int* in_sizes, int n_in,
                              void* d_out, int out_size) {
    const float* h  = (const float*)d_in[0];
    const float* e  = (const float*)d_in[1];
    const int*   src = (const int*)d_in[2];
    const int*   dst = (const int*)d_in[3];
    const float* Wq = (const float*)d_in[4];
    const float* bq = (const float*)d_in[5];
    const float* Wk = (const float*)d_in[6];
    const float* bk = (const float*)d_in[7];
    const float* We = (const float*)d_in[8];
    const float* be = (const float*)d_in[9];
    const float* Wv = (const float*)d_in[10];
    const float* bv = (const float*)d_in[11];
    float* out = (float*)d_out;

    cudaFuncSetAttribute(edge_score_mma_kernel,
                         cudaFuncAttributeMaxDynamicSharedMemorySize, SMEM_EDGE_TOTAL);

    // edge kernel at launch index 3 — the slot ncu's -s 5 -c 1 capture lands on
    prep_we_kernel<<<(DIM * DIM + 255) / 256, 256>>>(We);               // 0 (+ zeroes cnt)
    dim3 gq((N_NODES + 127) / 128, 3);
    qkv_kernel<<<gq, 256>>>(h, Wq, bq, Wk, bk, Wv, bv);                 // 1
    hist_kernel<<<(N_EDGES + 255) / 256, 256>>>(dst);                   // 2
    edge_score_mma_kernel<<<N_EDGES / 128, 128, SMEM_EDGE_TOTAL>>>(e, be, src, dst);  // 3
    scan_kernel<<<1, 1024>>>();                                         // 4
    scatter_kernel<<<(N_EDGES + 255) / 256, 256>>>(dst);                // 5
    aggregate_kernel<<<(N_NODES * 32 + 255) / 256, 256>>>(src, out);    // 6
}

// round 16
// speedup vs baseline: 2.1406x; 1.3219x over previous
#include <cuda_runtime.h>
#include <cuda_bf16.h>
#include <cuda_fp16.h>
#include <cstdint>

#define N_NODES 10000
#define N_EDGES 640000
#define DIM 128
#define NHEADS 8

typedef unsigned long long u64;

// ---------------- scratch (device globals; no allocation allowed) ----------------
__device__ float g_Q[N_NODES * DIM];
__device__ float g_K[N_NODES * DIM];
__device__ float g_V[N_NODES * DIM];
__device__ float g_s[(size_t)N_EDGES * NHEADS];
__device__ int   g_cnt[N_NODES];
__device__ int   g_start[N_NODES];
__device__ int   g_cursor[N_NODES];
__device__ int   g_elist[N_EDGES];
// We rounded to fp16, compact row-major [n=128][k=128] (single array; A carries
// the precision via its hi/lo split: a*b ~= (ah+al)*bh, err ~ 2^-12 rel)
__device__ __align__(16) __half g_Bhi[DIM * DIM];

// ---------------- fp32x2 helpers (QKV FFMA GEMM) ----------------
__device__ __forceinline__ u64 pack_dup(float a) {
    u64 r; asm("mov.b64 %0, {%1, %1};" : "=l"(r) : "f"(a)); return r;
}
__device__ __forceinline__ u64 fma2(u64 a, u64 b, u64 c) {
    u64 d; asm("fma.rn.f32x2 %0, %1, %2, %3;" : "=l"(d) : "l"(a), "l"(b), "l"(c)); return d;
}
__device__ __forceinline__ float2 unpack2(u64 v) {
    float lo, hi; asm("mov.b64 {%0, %1}, %2;" : "=f"(lo), "=f"(hi) : "l"(v));
    return make_float2(lo, hi);
}

// ---------------- fp16 mma.sync + ldmatrix (sm_80+ PTX, legal on target sm_103) ------
__device__ __forceinline__ void mma_f16(float* c, const uint32_t* a,
                                        uint32_t b0, uint32_t b1) {
    asm volatile(
        "mma.sync.aligned.m16n8k16.row.col.f32.f16.f16.f32 "
        "{%0,%1,%2,%3}, {%4,%5,%6,%7}, {%8,%9}, {%0,%1,%2,%3};"
        : "+f"(c[0]), "+f"(c[1]), "+f"(c[2]), "+f"(c[3])
        : "r"(a[0]), "r"(a[1]), "r"(a[2]), "r"(a[3]), "r"(b0), "r"(b1));
}

__device__ __forceinline__ void ldsm4(uint32_t& r0, uint32_t& r1, uint32_t& r2,
                                      uint32_t& r3, uint32_t addr) {
    asm volatile("ldmatrix.sync.aligned.m8n8.x4.shared.b16 {%0,%1,%2,%3}, [%4];"
                 : "=r"(r0), "=r"(r1), "=r"(r2), "=r"(r3) : "r"(addr));
}

__device__ __forceinline__ uint32_t smem_u32(const void* p) {
    uint32_t a;
    asm("{ .reg .u64 t; cvta.to.shared.u64 t, %1; cvt.u32.u64 %0, t; }" : "=r"(a) : "l"(p));
    return a;
}

// XOR swizzle for 256B fp16 rows (conflict-free frag loads)
__device__ __forceinline__ int swz(int row, int kb) {
    return row * 256 + (kb ^ ((row & 7) << 4));
}

// split a float2 into fp16 hi-pair / lo-pair (packed u32 each)
__device__ __forceinline__ void split2h(float2 v, uint32_t& hi, uint32_t& lo) {
    __half2 h = __floats2half2_rn(v.x, v.y);
    float r0 = v.x - __half2float(__low2half(h));
    float r1 = v.y - __half2float(__high2half(h));
    __half2 l = __floats2half2_rn(r0, r1);
    hi = *(uint32_t*)&h;
    lo = *(uint32_t*)&l;
}

// ---------------- prep: round We to fp16 + zero CSR counters ----------------
__global__ void prep_we_kernel(const float* __restrict__ We) {
    int idx = blockIdx.x * blockDim.x + threadIdx.x;
    if (idx < N_NODES) { g_cnt[idx] = 0; g_cursor[idx] = 0; }
    if (idx >= DIM * DIM) return;
    g_Bhi[idx] = __float2half(We[idx]);
}

// ---------------- QKV projections (FFMA, small) ----------------
#define SPAD 132
template <bool GUARD>
__device__ __forceinline__ void load_slab(const float* __restrict__ src, int row0,
                                          int maxrow, int j0,
                                          float (*dst)[SPAD], int tid) {
#pragma unroll
    for (int r = 0; r < 4; r++) {
        int idx = tid + r * 256;
        int row = idx >> 3;
        int jq  = idx & 7;
        float4 v = make_float4(0.f, 0.f, 0.f, 0.f);
        int gr = row0 + row;
        if (!GUARD || gr < maxrow)
            v = *(const float4*)(src + (size_t)gr * DIM + j0 + jq * 4);
        dst[jq * 4 + 0][row] = v.x;
        dst[jq * 4 + 1][row] = v.y;
        dst[jq * 4 + 2][row] = v.z;
        dst[jq * 4 + 3][row] = v.w;
    }
}

__device__ __forceinline__ void gemm_inner(const float (*As)[SPAD],
                                           const float (*Ws)[SPAD],
                                           u64 acc[8][4], int tx, int ty) {
#pragma unroll 4
    for (int j = 0; j < 32; j++) {
        float4 a0 = *(const float4*)&As[j][ty * 8];
        float4 a1 = *(const float4*)&As[j][ty * 8 + 4];
        const u64* wp = (const u64*)&Ws[j][tx * 8];
        u64 w0 = wp[0], w1 = wp[1], w2 = wp[2], w3 = wp[3];
        float a[8] = {a0.x, a0.y, a0.z, a0.w, a1.x, a1.y, a1.z, a1.w};
#pragma unroll
        for (int i = 0; i < 8; i++) {
            u64 ad = pack_dup(a[i]);
            acc[i][0] = fma2(ad, w0, acc[i][0]);
            acc[i][1] = fma2(ad, w1, acc[i][1]);
            acc[i][2] = fma2(ad, w2, acc[i][2]);
            acc[i][3] = fma2(ad, w3, acc[i][3]);
        }
    }
}

__global__ __launch_bounds__(256, 2) void qkv_kernel(
    const float* __restrict__ h,
    const float* __restrict__ Wq, const float* __restrict__ bq,
    const float* __restrict__ Wk, const float* __restrict__ bk,
    const float* __restrict__ Wv, const float* __restrict__ bv) {
    __shared__ float As[32][SPAD];
    __shared__ float Ws[32][SPAD];

    const float* W; const float* b; float* out;
    if (blockIdx.y == 0)      { W = Wq; b = bq; out = g_Q; }
    else if (blockIdx.y == 1) { W = Wk; b = bk; out = g_K; }
    else                      { W = Wv; b = bv; out = g_V; }

    int tid = threadIdx.x;
    int tx = tid & 15, ty = tid >> 4;
    int m0 = blockIdx.x * 128;

    u64 acc[8][4];
#pragma unroll
    for (int i = 0; i < 8; i++)
#pragma unroll
        for (int k = 0; k < 4; k++) acc[i][k] = 0ull;

    for (int kt = 0; kt < 4; kt++) {
        load_slab<true>(h, m0, N_NODES, kt * 32, As, tid);
        load_slab<false>(W, 0, 128, kt * 32, Ws, tid);
        __syncthreads();
        gemm_inner(As, Ws, acc, tx, ty);
        __syncthreads();
    }

    float4 b0 = *(const float4*)(b + tx * 8);
    float4 b1 = *(const float4*)(b + tx * 8 + 4);
#pragma unroll
    for (int i = 0; i < 8; i++) {
        int m = m0 + ty * 8 + i;
        if (m < N_NODES) {
            float2 p0 = unpack2(acc[i][0]);
            float2 p1 = unpack2(acc[i][1]);
            float2 p2 = unpack2(acc[i][2]);
            float2 p3 = unpack2(acc[i][3]);
            float4 o0 = make_float4(p0.x + b0.x, p0.y + b0.y, p1.x + b0.z, p1.y + b0.w);
            float4 o1 = make_float4(p2.x + b1.x, p2.y + b1.y, p3.x + b1.z, p3.y + b1.w);
            *(float4*)(out + (size_t)m * DIM + tx * 8)     = o0;
            *(float4*)(out + (size_t)m * DIM + tx * 8 + 4) = o1;
        }
    }
}

// ---------------- edge projection: mma.sync fp16 2-term, M=32/warp, 3 CTAs/SM -------
// Dynamic smem: B_hi only [0,32KB). 128 threads, 3 CTAs/SM (12 warps).
// Each ldsm.x4 fetches both k-chunks for TWO n-fragments (lanes 0-15: n, 16-31: n+1).
#define SMEM_EDGE_TOTAL 32768

__global__ __launch_bounds__(128, 3)
void edge_score_mma_kernel(const float* __restrict__ e,
                           const float* __restrict__ be,
                           const int* __restrict__ src,
                           const int* __restrict__ dst) {
    extern __shared__ char smem[];
    int tid = threadIdx.x;
    int lane = tid & 31;
    int wid = tid >> 5;

    // --- copy We (fp16) into swizzled smem (32KB, L2-resident source) ---
    {
        const uint4* sh = (const uint4*)g_Bhi;
#pragma unroll
        for (int it = 0; it < 16; it++) {
            int i = tid + it * 128;      // 2048 16B-chunks
            int row = i >> 4, q = i & 15;
            int off = swz(row, q * 16);
            *(uint4*)(smem + off) = sh[i];
        }
    }
    __syncthreads();

    // --- fragment geometry: warp owns rows [wid*32, wid*32+32) (2 m16 tiles) ---
    int qd = lane & 3;                    // quad lane
    int wm = wid * 32 + (lane >> 2);      // tile0 rows: wm, wm+8; tile1: wm+16, wm+24
    int e0 = blockIdx.x * 128 + wm;
    const float* eBase = e + (size_t)e0 * DIM + qd * 2;  // rows via immediate offsets

    // per-lane ldmatrix base: lanes 0-7: frag n chunk0, 8-15: frag n chunk1,
    //                         16-23: frag n+1 chunk0, 24-31: frag n+1 chunk1
    int lr = lane & 7;
    int npair = (lane >> 4) & 1;
    uint32_t sb = smem_u32(smem);
    uint32_t ldbase = sb + npair * 2048 + lr * 256;
    int sel1 = ((lane >> 3) & 1) * 16;

    float acc0[16][4], acc1[16][4];
#pragma unroll
    for (int n = 0; n < 16; n++)
#pragma unroll
        for (int j = 0; j < 4; j++) { acc0[n][j] = 0.f; acc1[n][j] = 0.f; }

#pragma unroll 1
    for (int ks = 0; ks < 8; ks++) {
        int o = ks * 16;
        // A fragments straight from global (quad reads 32B-contiguous), split hi/lo
        float2 f0 = *(const float2*)(eBase + o);
        float2 f1 = *(const float2*)(eBase + o + 8 * DIM);
        float2 f2 = *(const float2*)(eBase + o + 8);
        float2 f3 = *(const float2*)(eBase + o + 8 * DIM + 8);
        float2 f4 = *(const float2*)(eBase + o + 16 * DIM);
        float2 f5 = *(const float2*)(eBase + o + 24 * DIM);
        float2 f6 = *(const float2*)(eBase + o + 16 * DIM + 8);
        float2 f7 = *(const float2*)(eBase + o + 24 * DIM + 8);
        uint32_t ah0[4], al0[4], ah1[4], al1[4];
        split2h(f0, ah0[0], al0[0]);
        split2h(f1, ah0[1], al0[1]);
        split2h(f2, ah0[2], al0[2]);
        split2h(f3, ah0[3], al0[3]);
        split2h(f4, ah1[0], al1[0]);
        split2h(f5, ah1[1], al1[1]);
        split2h(f6, ah1[2], al1[2]);
        split2h(f7, ah1[3], al1[3]);

        uint32_t lda = ldbase + ((uint32_t)(ks * 32 + sel1) ^ (uint32_t)(lr * 16));
#pragma unroll
        for (int n = 0; n < 16; n += 2) {
            uint32_t b0, b1, b2, b3;     // frag n: b0,b1; frag n+1: b2,b3
            ldsm4(b0, b1, b2, b3, lda + n * 2048);
            mma_f16(acc0[n], ah0, b0, b1);
            mma_f16(acc0[n], al0, b0, b1);
            mma_f16(acc1[n], ah1, b0, b1);
            mma_f16(acc1[n], al1, b0, b1);
            mma_f16(acc0[n + 1], ah0, b2, b3);
            mma_f16(acc0[n + 1], al0, b2, b3);
            mma_f16(acc1[n + 1], ah1, b2, b3);
            mma_f16(acc1[n + 1], al1, b2, b3);
        }
    }

    // --- register epilogue (R13-proven): score = exp(clamp(sum (E+be)*K*Q /4)) ---
#pragma unroll
    for (int t = 0; t < 2; t++) {
        int r0 = e0 + t * 16;            // rows r0, r0+8
        int r1 = r0 + 8;
        int s0 = src[r0], d0 = dst[r0];
        int s1 = src[r1], d1 = dst[r1];
        const float* K0p = g_K + (size_t)s0 * DIM + qd * 2;
        const float* Q0p = g_Q + (size_t)d0 * DIM + qd * 2;
        const float* K1p = g_K + (size_t)s1 * DIM + qd * 2;
        const float* Q1p = g_Q + (size_t)d1 * DIM + qd * 2;

        float hs0[8], hs1[8];
#pragma unroll
        for (int hh = 0; hh < 8; hh++) { hs0[hh] = 0.f; hs1[hh] = 0.f; }

#pragma unroll
        for (int n = 0; n < 16; n++) {
            int c = n * 8;
            float2 bb = *(const float2*)(be + c + qd * 2);
            float2 K0 = *(const float2*)(K0p + c);
            float2 Q0 = *(const float2*)(Q0p + c);
            float2 K1 = *(const float2*)(K1p + c);
            float2 Q1 = *(const float2*)(Q1p + c);
            const float* a = t == 0 ? acc0[n] : acc1[n];
            int hh = n >> 1;
            hs0[hh] += (a[0] + bb.x) * K0.x * Q0.x + (a[1] + bb.y) * K0.y * Q0.y;
            hs1[hh] += (a[2] + bb.x) * K1.x * Q1.x + (a[3] + bb.y) * K1.y * Q1.y;
        }
#pragma unroll
        for (int hh = 0; hh < 8; hh++) {
            hs0[hh] += __shfl_xor_sync(0xffffffffu, hs0[hh], 1);
            hs0[hh] += __shfl_xor_sync(0xffffffffu, hs0[hh], 2);
            hs1[hh] += __shfl_xor_sync(0xffffffffu, hs1[hh], 1);
            hs1[hh] += __shfl_xor_sync(0xffffffffu, hs1[hh], 2);
        }
#pragma unroll
        for (int j = 0; j < 2; j++) {
            int hh = 2 * qd + j;
            float v0, v1;
#pragma unroll
            for (int x = 0; x < 8; x++) {
                if (x == hh) { v0 = hs0[x]; v1 = hs1[x]; }
            }
            float sc0 = fminf(fmaxf(v0 * 0.25f, -5.0f), 5.0f);
            float sc1 = fminf(fmaxf(v1 * 0.25f, -5.0f), 5.0f);
            g_s[(size_t)r0 * NHEADS + hh] = __expf(sc0);
            g_s[(size_t)r1 * NHEADS + hh] = __expf(sc1);
        }
    }
}

// ---------------- CSR build (by dst) ----------------
__global__ void hist_kernel(const int* __restrict__ dst) {
    int e0 = blockIdx.x * blockDim.x + threadIdx.x;
    if (e0 < N_EDGES) atomicAdd(&g_cnt[dst[e0]], 1);
}

__global__ void scan_kernel() {
    __shared__ int sm[1024];
    int t = threadIdx.x;
    const int CH = 10;
    int base = t * CH;
    int s = 0;
#pragma unroll
    for (int c = 0; c < CH; c++) {
        int i = base + c;
        if (i < N_NODES) s += g_cnt[i];
    }
    sm[t] = s;
    __syncthreads();
    for (int off = 1; off < 1024; off <<= 1) {
        int v = (t >= off) ? sm[t - off] : 0;
        __syncthreads();
        sm[t] += v;
        __syncthreads();
    }
    int run = sm[t] - s;
#pragma unroll
    for (int c = 0; c < CH; c++) {
        int i = base + c;
        if (i < N_NODES) {
            g_start[i] = run;
            run += g_cnt[i];
        }
    }
}

__global__ void scatter_kernel(const int* __restrict__ dst) {
    int e0 = blockIdx.x * blockDim.x + threadIdx.x;
    if (e0 < N_EDGES) {
        int d = dst[e0];
        int p = atomicAdd(&g_cursor[d], 1);
        g_elist[g_start[d] + p] = e0;
    }
}

// ---------------- per-dst gather aggregation (unroll-4 MLP) ----------------
__global__ void aggregate_kernel(const int* __restrict__ src,
                                 float* __restrict__ out) {
    int warp = (blockIdx.x * blockDim.x + threadIdx.x) >> 5;
    int lane = threadIdx.x & 31;
    if (warp >= N_NODES) return;
    int st = g_start[warp];
    int cn = g_cnt[warp];
    int hh = lane >> 2;
    float a0 = 0.f, a1 = 0.f, a2 = 0.f, a3 = 0.f, z = 0.f;
    int k = 0;
    for (; k + 4 <= cn; k += 4) {
        int i0 = g_elist[st + k];
        int i1 = g_elist[st + k + 1];
        int i2 = g_elist[st + k + 2];
        int i3 = g_elist[st + k + 3];
        float s0 = g_s[(size_t)i0 * NHEADS + hh];
        float s1 = g_s[(size_t)i1 * NHEADS + hh];
        float s2 = g_s[(size_t)i2 * NHEADS + hh];
        float s3 = g_s[(size_t)i3 * NHEADS + hh];
        float4 v0 = *(const float4*)(g_V + (size_t)src[i0] * DIM + lane * 4);
        float4 v1 = *(const float4*)(g_V + (size_t)src[i1] * DIM + lane * 4);
        float4 v2 = *(const float4*)(g_V + (size_t)src[i2] * DIM + lane * 4);
        float4 v3 = *(const float4*)(g_V + (size_t)src[i3] * DIM + lane * 4);
        a0 += v0.x * s0 + v1.x * s1 + v2.x * s2 + v3.x * s3;
        a1 += v0.y * s0 + v1.y * s1 + v2.y * s2 + v3.y * s3;
        a2 += v0.z * s0 + v1.z * s1 + v2.z * s2 + v3.z * s3;
        a3 += v0.w * s0 + v1.w * s1 + v2.w * s2 + v3.w * s3;
        z += s0 + s1 + s2 + s3;
    }
    for (; k < cn; k++) {
        int eidx = g_elist[st + k];
        float s = g_s[(size_t)eidx * NHEADS + hh];
        float4 v = *(const float4*)(g_V + (size_t)src[eidx] * DIM + lane * 4);
        a0 += v.x * s;
        a1 += v.y * s;
        a2 += v.z * s;
        a3 += v.w * s;
        z += s;
    }
    float inv = 1.0f / (z + 1e-6f);
    float4 o = make_float4(a0 * inv, a1 * inv, a2 * inv, a3 * inv);
    *(float4*)(out + (size_t)warp * DIM + lane * 4) = o;
}

// ---------------- launch ----------------
extern "C" void kernel_launch(void* const* d_in, const int* in_sizes, int n_in,
                              void* d_out, int out_size) {
    const float* h  = (const float*)d_in[0];
    const float* e  = (const float*)d_in[1];
    const int*   src = (const int*)d_in[2];
    const int*   dst = (const int*)d_in[3];
    const float* Wq = (const float*)d_in[4];
    const float* bq = (const float*)d_in[5];
    const float* Wk = (const float*)d_in[6];
    const float* bk = (const float*)d_in[7];
    const float* We = (const float*)d_in[8];
    const float* be = (const float*)d_in[9];
    const float* Wv = (const float*)d_in[10];
    const float* bv = (const float*)d_in[11];
    float* out = (float*)d_out;

    cudaFuncSetAttribute(edge_score_mma_kernel,
                         cudaFuncAttributeMaxDynamicSharedMemorySize, SMEM_EDGE_TOTAL);

    // edge kernel at launch index 3 — the slot ncu's -s 5 -c 1 capture lands on
    prep_we_kernel<<<(DIM * DIM + 255) / 256, 256>>>(We);               // 0 (+ zeroes cnt)
    dim3 gq((N_NODES + 127) / 128, 3);
    qkv_kernel<<<gq, 256>>>(h, Wq, bq, Wk, bk, Wv, bv);                 // 1
    hist_kernel<<<(N_EDGES + 255) / 256, 256>>>(dst);                   // 2
    edge_score_mma_kernel<<<N_EDGES / 128, 128, SMEM_EDGE_TOTAL>>>(e, be, src, dst);  // 3
    scan_kernel<<<1, 1024>>>();                                         // 4
    scatter_kernel<<<(N_EDGES + 255) / 256, 256>>>(dst);                // 5
    aggregate_kernel<<<(N_NODES * 32 + 255) / 256, 256>>>(src, out);    // 6
}